// round 16
// baseline (speedup 1.0000x reference)
#include <cuda_runtime.h>
#include <math.h>

#define N_NODES 10000
#define N_EDGES 100000

#define INV_SQRT3    0.57735026918962576f
#define NORM_MSG     0.036084391824351614f   // 1/sqrt(768)
#define NORM_MSG_V3  (0.036084391824351614f * 0.57735026918962576f)
#define NORM_UPD_S   0.011811391307201575f   // 1/sqrt(7168)
#define NORM_UPD_V   0.013975424859373686f   // 1/sqrt(5120)
#define NORM_LIN64   0.125f                  // 1/sqrt(64)
#define NORM_LIN32   0.17677669529663687f    // 1/sqrt(32)

#define ZSTRIDE 4096
// per-node factored message tensor product (norms folded in):
// [0,768) Zss[v<8][w<96], [768,3072) Zvv[(v*3+m)<24][w<96],
// [3072,3328) Zsv[v<8][w<32], [3328,4096) Zvs[v<8][(w*3+m)<96]
__device__ float g_z[(size_t)N_NODES * ZSTRIDE];
__device__ float g_agg[N_NODES * 192];   // [96 scalars | 32x3 vectors] per node
__device__ float g_upd[N_NODES * 192];   // raw partial sums: us[96] | uv[u*3+m]

__global__ void zero_kernel() {
    int i = blockIdx.x * blockDim.x + threadIdx.x;
    if (i < N_NODES * 192) { g_agg[i] = 0.f; g_upd[i] = 0.f; }
}

// ============================================================================
// Z PRECOMPUTE v2 (committed): 32 nodes/block, 256 threads, reg-tiled GEMMs.
// ============================================================================
__global__ void __launch_bounds__(256) precompute_z(
    const float* __restrict__ nf,
    const float* __restrict__ Wss, const float* __restrict__ Wvv,
    const float* __restrict__ Wsv, const float* __restrict__ Wvs)
{
    __shared__ float s_xsT[64 * 32];
    __shared__ float s_xvT[3 * 32 * 32];
    __shared__ float s_W[64 * 64];

    const int t  = threadIdx.x;
    const int n0 = blockIdx.x * 32;

    for (int i = t; i < 32 * 160; i += 256) {
        int n = i / 160, c = i - n * 160;
        int gn = n0 + n;
        float v = (gn < N_NODES) ? nf[(size_t)gn * 160 + c] : 0.f;
        if (c < 64) s_xsT[c * 32 + n] = v;
        else { int c2 = c - 64, u = c2 / 3, m = c2 - u * 3;
               s_xvT[m * 1024 + u * 32 + n] = v; }
    }
    __syncthreads();

    const int tc = t & 31;
    const int tn = t >> 5;
    const int c2 = tc * 2;
    const int n4 = tn * 4;
    const int gnb = n0 + n4;

    for (int p = 0; p < 12; p++) {
        for (int idx = t; idx < 4096; idx += 256) {
            int u = idx >> 6, cc = idx & 63;
            s_W[idx] = Wss[u * 768 + p * 64 + cc];
        }
        __syncthreads();
        float acc[8];
        #pragma unroll
        for (int i = 0; i < 8; i++) acc[i] = 0.f;
        #pragma unroll 8
        for (int u = 0; u < 64; u++) {
            float2 w = *(const float2*)&s_W[u * 64 + c2];
            float4 x = *(const float4*)&s_xsT[u * 32 + n4];
            acc[0] = fmaf(w.x, x.x, acc[0]);
            acc[1] = fmaf(w.x, x.y, acc[1]);
            acc[2] = fmaf(w.x, x.z, acc[2]);
            acc[3] = fmaf(w.x, x.w, acc[3]);
            acc[4] = fmaf(w.y, x.x, acc[4]);
            acc[5] = fmaf(w.y, x.y, acc[5]);
            acc[6] = fmaf(w.y, x.z, acc[6]);
            acc[7] = fmaf(w.y, x.w, acc[7]);
        }
        #pragma unroll
        for (int nn = 0; nn < 4; nn++) {
            int gn = gnb + nn;
            if (gn < N_NODES) {
                float2 o = { acc[nn] * NORM_MSG, acc[4 + nn] * NORM_MSG };
                *(float2*)&g_z[(size_t)gn * ZSTRIDE + p * 64 + c2] = o;
            }
        }
        __syncthreads();
    }

    for (int m = 0; m < 3; m++) {
        const float* xm = s_xvT + m * 1024;
        for (int p = 0; p < 12; p++) {
            for (int idx = t; idx < 2048; idx += 256) {
                int u = idx >> 6, cc = idx & 63;
                s_W[idx] = Wvv[u * 768 + p * 64 + cc];
            }
            __syncthreads();
            float acc[8];
            #pragma unroll
            for (int i = 0; i < 8; i++) acc[i] = 0.f;
            #pragma unroll 8
            for (int u = 0; u < 32; u++) {
                float2 w = *(const float2*)&s_W[u * 64 + c2];
                float4 x = *(const float4*)&xm[u * 32 + n4];
                acc[0] = fmaf(w.x, x.x, acc[0]);
                acc[1] = fmaf(w.x, x.y, acc[1]);
                acc[2] = fmaf(w.x, x.z, acc[2]);
                acc[3] = fmaf(w.x, x.w, acc[3]);
                acc[4] = fmaf(w.y, x.x, acc[4]);
                acc[5] = fmaf(w.y, x.y, acc[5]);
                acc[6] = fmaf(w.y, x.z, acc[6]);
                acc[7] = fmaf(w.y, x.w, acc[7]);
            }
            int cm = p * 64 + c2;
            int v  = cm / 96;
            int col = 768 + v * 288 + m * 96 + (cm - v * 96);
            #pragma unroll
            for (int nn = 0; nn < 4; nn++) {
                int gn = gnb + nn;
                if (gn < N_NODES) {
                    float2 o = { acc[nn] * NORM_MSG_V3, acc[4 + nn] * NORM_MSG_V3 };
                    *(float2*)&g_z[(size_t)gn * ZSTRIDE + col] = o;
                }
            }
            __syncthreads();
        }
    }

    for (int p = 0; p < 4; p++) {
        for (int idx = t; idx < 4096; idx += 256) {
            int u = idx >> 6, cc = idx & 63;
            s_W[idx] = Wsv[u * 256 + p * 64 + cc];
        }
        __syncthreads();
        float acc[8];
        #pragma unroll
        for (int i = 0; i < 8; i++) acc[i] = 0.f;
        #pragma unroll 8
        for (int u = 0; u < 64; u++) {
            float2 w = *(const float2*)&s_W[u * 64 + c2];
            float4 x = *(const float4*)&s_xsT[u * 32 + n4];
            acc[0] = fmaf(w.x, x.x, acc[0]);
            acc[1] = fmaf(w.x, x.y, acc[1]);
            acc[2] = fmaf(w.x, x.z, acc[2]);
            acc[3] = fmaf(w.x, x.w, acc[3]);
            acc[4] = fmaf(w.y, x.x, acc[4]);
            acc[5] = fmaf(w.y, x.y, acc[5]);
            acc[6] = fmaf(w.y, x.z, acc[6]);
            acc[7] = fmaf(w.y, x.w, acc[7]);
        }
        #pragma unroll
        for (int nn = 0; nn < 4; nn++) {
            int gn = gnb + nn;
            if (gn < N_NODES) {
                float2 o = { acc[nn] * NORM_MSG, acc[4 + nn] * NORM_MSG };
                *(float2*)&g_z[(size_t)gn * ZSTRIDE + 3072 + p * 64 + c2] = o;
            }
        }
        __syncthreads();
    }

    for (int p = 0; p < 8; p++) {
        for (int idx = t; idx < 1024; idx += 256) {
            int u = idx >> 5, cw = idx & 31;
            s_W[idx] = Wvs[u * 256 + p * 32 + cw];
        }
        __syncthreads();
        float acc[12];
        #pragma unroll
        for (int i = 0; i < 12; i++) acc[i] = 0.f;
        #pragma unroll 8
        for (int u = 0; u < 32; u++) {
            float w = s_W[u * 32 + tc];
            #pragma unroll
            for (int m = 0; m < 3; m++) {
                float4 x = *(const float4*)&s_xvT[m * 1024 + u * 32 + n4];
                acc[m * 4 + 0] = fmaf(w, x.x, acc[m * 4 + 0]);
                acc[m * 4 + 1] = fmaf(w, x.y, acc[m * 4 + 1]);
                acc[m * 4 + 2] = fmaf(w, x.z, acc[m * 4 + 2]);
                acc[m * 4 + 3] = fmaf(w, x.w, acc[m * 4 + 3]);
            }
        }
        int cw = p * 32 + tc;
        int v  = cw >> 5, ww = cw & 31;
        int colb = 3328 + v * 96 + ww * 3;
        #pragma unroll
        for (int nn = 0; nn < 4; nn++) {
            int gn = gnb + nn;
            if (gn < N_NODES) {
                float* dst = &g_z[(size_t)gn * ZSTRIDE + colb];
                #pragma unroll
                for (int m = 0; m < 3; m++)
                    dst[m] = acc[m * 4 + nn] * NORM_MSG;
            }
        }
        __syncthreads();
    }
}

// ============================================================================
// EDGE KERNEL v3: 32 edges/block, 256 threads.
// Phase 1: warp handles 4 edges INTERLEAVED (12 accumulators, full MLP).
// Phase 2: linear layers as block GEMMs (R12, verified) -> atomic scatter.
// smem (floats): WLs 6144 | WLv 1024 | y 1024 | msT 64x34 | mvT 96x34 | row 32
// ============================================================================
#define EB 32
#define EDGE_SMEM_BYTES (13664 * 4)

__global__ void __launch_bounds__(256) edge_kernel(
    const float* __restrict__ ea,
    const float* __restrict__ WLs, const float* __restrict__ WLv,
    const int* __restrict__ eidx)
{
    extern __shared__ float sme[];
    float* s_WLs = sme;            // 6144
    float* s_WLv = sme + 6144;     // 1024
    float* s_y   = sme + 7168;     // 1024  [e][c]
    float* s_msT = sme + 8192;     // 2176  [u<64][34] silu'd plain
    float* s_mvT = sme + 10368;    // 3264  [(m*32+w)<96][34] gated
    int*   s_row = (int*)(sme + 13632);

    const int t  = threadIdx.x;
    const int e0 = blockIdx.x * EB;

    for (int i = t; i < 6144; i += 256) s_WLs[i] = WLs[i];
    for (int i = t; i < 1024; i += 256) s_WLv[i] = WLv[i];
    for (int i = t; i < 1024; i += 256) s_y[i] = ea[(size_t)e0 * 32 + i];
    if (t < EB) s_row[t] = eidx[e0 + t];
    __syncthreads();

    const int wid = t >> 5, l = t & 31;
    const int eb4 = wid * 4;

    const float* Zp[4];
    #pragma unroll
    for (int j = 0; j < 4; j++)
        Zp[j] = g_z + (size_t)eidx[N_EDGES + e0 + eb4 + j] * ZSTRIDE;

    // ---- phase 1a: scalar TP, 4 edges interleaved (12 acc, 12 loads/q) ----
    float a[12];
    #pragma unroll
    for (int i = 0; i < 12; i++) a[i] = 0.f;
    #pragma unroll 4
    for (int q = 0; q < 32; q++) {
        #pragma unroll
        for (int j = 0; j < 4; j++) {
            float y = s_y[(eb4 + j) * 32 + q];
            const float* zr = Zp[j] + q * 96;
            a[j * 3 + 0] = fmaf(y, zr[l],      a[j * 3 + 0]);
            a[j * 3 + 1] = fmaf(y, zr[l + 32], a[j * 3 + 1]);
            a[j * 3 + 2] = fmaf(y, zr[l + 64], a[j * 3 + 2]);
        }
    }
    float g[4];
    #pragma unroll
    for (int j = 0; j < 4; j++) {
        int el = eb4 + j;
        float p0 = a[j * 3 + 0], p1 = a[j * 3 + 1];
        s_msT[l * 34 + el]        = p0 / (1.f + expf(-p0));
        s_msT[(32 + l) * 34 + el] = p1 / (1.f + expf(-p1));
        g[j] = 1.f / (1.f + expf(-a[j * 3 + 2]));
    }

    // ---- phase 1b: vector TP, 4 edges interleaved per (cc) ----
    #pragma unroll
    for (int cc = 0; cc < 3; cc++) {
        int c = l + cc * 32;
        int w = c / 3, m = c - w * 3;
        float acc[4] = {0.f, 0.f, 0.f, 0.f};
        #pragma unroll
        for (int v = 0; v < 8; v++) {
            #pragma unroll
            for (int j = 0; j < 4; j++) {
                const float* ye = s_y + (eb4 + j) * 32;
                acc[j] = fmaf(ye[v],             Zp[j][3328 + v * 96 + c], acc[j]);
                acc[j] = fmaf(ye[8 + v * 3 + m], Zp[j][3072 + v * 32 + w], acc[j]);
            }
        }
        #pragma unroll
        for (int j = 0; j < 4; j++) {
            float gw = __shfl_sync(0xffffffffu, g[j], w);
            s_mvT[(m * 32 + w) * 34 + eb4 + j] = acc[j] * gw;
        }
    }
    __syncthreads();

    // ---- phase 2a: scalar linear GEMM [32e x 64] x [64 x 96] ----
    {
        const int te2 = (t >> 4) * 2;
        const int tw6 = (t & 15) * 6;
        float acc[12];
        #pragma unroll
        for (int i = 0; i < 12; i++) acc[i] = 0.f;
        #pragma unroll 8
        for (int u = 0; u < 64; u++) {
            float2 av = *(const float2*)&s_msT[u * 34 + te2];
            float2 b0 = *(const float2*)&s_WLs[u * 96 + tw6];
            float2 b1 = *(const float2*)&s_WLs[u * 96 + tw6 + 2];
            float2 b2 = *(const float2*)&s_WLs[u * 96 + tw6 + 4];
            acc[0]  = fmaf(av.x, b0.x, acc[0]);
            acc[1]  = fmaf(av.x, b0.y, acc[1]);
            acc[2]  = fmaf(av.x, b1.x, acc[2]);
            acc[3]  = fmaf(av.x, b1.y, acc[3]);
            acc[4]  = fmaf(av.x, b2.x, acc[4]);
            acc[5]  = fmaf(av.x, b2.y, acc[5]);
            acc[6]  = fmaf(av.y, b0.x, acc[6]);
            acc[7]  = fmaf(av.y, b0.y, acc[7]);
            acc[8]  = fmaf(av.y, b1.x, acc[8]);
            acc[9]  = fmaf(av.y, b1.y, acc[9]);
            acc[10] = fmaf(av.y, b2.x, acc[10]);
            acc[11] = fmaf(av.y, b2.y, acc[11]);
        }
        const size_t r0 = (size_t)s_row[te2]     * 192;
        const size_t r1 = (size_t)s_row[te2 + 1] * 192;
        #pragma unroll
        for (int jj = 0; jj < 6; jj++) {
            atomicAdd(&g_agg[r0 + tw6 + jj], acc[jj]     * NORM_LIN64);
            atomicAdd(&g_agg[r1 + tw6 + jj], acc[6 + jj] * NORM_LIN64);
        }
    }

    // ---- phase 2b: vector linear, 3 GEMMs [32e x 32] x [32 x 32] ----
    {
        const int te2 = (t >> 4) * 2;
        const int tw2 = (t & 15) * 2;
        float acc[12];   // [m][ei][wj]
        #pragma unroll
        for (int i = 0; i < 12; i++) acc[i] = 0.f;
        #pragma unroll 8
        for (int u = 0; u < 32; u++) {
            float2 b = *(const float2*)&s_WLv[u * 32 + tw2];
            #pragma unroll
            for (int m = 0; m < 3; m++) {
                float2 av = *(const float2*)&s_mvT[(m * 32 + u) * 34 + te2];
                acc[m * 4 + 0] = fmaf(av.x, b.x, acc[m * 4 + 0]);
                acc[m * 4 + 1] = fmaf(av.x, b.y, acc[m * 4 + 1]);
                acc[m * 4 + 2] = fmaf(av.y, b.x, acc[m * 4 + 2]);
                acc[m * 4 + 3] = fmaf(av.y, b.y, acc[m * 4 + 3]);
            }
        }
        const size_t r0 = (size_t)s_row[te2]     * 192 + 96;
        const size_t r1 = (size_t)s_row[te2 + 1] * 192 + 96;
        #pragma unroll
        for (int m = 0; m < 3; m++) {
            #pragma unroll
            for (int jj = 0; jj < 2; jj++) {
                atomicAdd(&g_agg[r0 + (tw2 + jj) * 3 + m], acc[m * 4 + jj]     * NORM_LIN32);
                atomicAdd(&g_agg[r1 + (tw2 + jj) * 3 + m], acc[m * 4 + 2 + jj] * NORM_LIN32);
            }
        }
    }
}

// ============================================================================
// NODE KERNEL v7 (committed @716us): ALU-free steady state, 8-way K-split,
// Kc=8, 128 threads, 4 blocks/SM.
// ============================================================================
#define KSPLIT 8
#define NODE_SMEM_BYTES (13312 * 4)

__global__ void __launch_bounds__(128, 4) node_kernel(
    const float* __restrict__ nf,
    const float* __restrict__ Wss, const float* __restrict__ Wvv,
    const float* __restrict__ Wsv, const float* __restrict__ Wvs)
{
    extern __shared__ float sm[];
    float* s_xsT = sm;
    float* s_xvT = sm + 2048;
    float* s_asT = sm + 5120;
    float* s_avT = sm + 8192;
    float* sCh   = sm + 11264;   // 2 x 1024

    const int t     = threadIdx.x;
    const int tile  = blockIdx.x >> 3;
    const int slice = blockIdx.x & 7;
    const int n0    = tile * 32;

    for (int i = t; i < 32 * 160; i += 128) {
        int n = i / 160, c = i - n * 160;
        int gn = n0 + n;
        float v = (gn < N_NODES) ? nf[gn * 160 + c] : 0.f;
        if (c < 64) s_xsT[c * 32 + n] = v;
        else { int c2 = c - 64, u = c2 / 3, m = c2 - u * 3;
               s_xvT[m * 1024 + u * 32 + n] = v; }
    }
    for (int i = t; i < 32 * 192; i += 128) {
        int n = i / 192, c = i - n * 192;
        int gn = n0 + n;
        float v = (gn < N_NODES) ? g_agg[gn * 192 + c] : 0.f;
        if (c < 96) s_asT[c * 32 + n] = v;
        else { int c2 = c - 96, w = c2 / 3, m = c2 - w * 3;
               s_avT[m * 1024 + w * 32 + n] = v; }
    }
    __syncthreads();

    const int kb  = t >> 4;
    const int n2b = (t & 15) * 2;
    const int wB6 = (t & 15) * 6;
    const int r6b = (t & 15) * 6;
    const int w2B = (t & 15) * 2;
    const int stA1 = kb * 32 + n2b;
    const int stB1 = kb * 96 + wB6;
    const int stA2 = kb * 96 + r6b;
    const int stB2 = kb * 32 + w2B;

    // ---------------- stage 1: us partial, 112 chunks of 8 ----------------
    {
        const int k_off = slice * 896;
        int c1 = (6144 - k_off) >> 3;
        if (c1 < 0) c1 = 0; if (c1 > 112) c1 = 112;

        const int ng = (t & 7) * 4;
        const int w6 = (t >> 3) * 6;
        float acc[24];
        #pragma unroll
        for (int i = 0; i < 24; i++) acc[i] = 0.f;

        const int ka0 = k_off + kb;
        int ua32 = (ka0 / 96) * 32;
        int va32 = (ka0 - (ka0 / 96) * 96) * 32;
        const int k2c1 = k_off + c1 * 8 + kb - 6144;
        int uu32 = (k2c1 >> 5) * 32;
        int vv32 = (k2c1 & 31) * 32;
        const float* pBvv0 = Wvv + k2c1 * 96 + wB6;
        const float* pB = (c1 > 0) ? (Wss + ka0 * 96 + wB6) : pBvv0;

        auto buildA1 = [&](int cc) -> float2 {
            float2 r;
            if (cc < c1) {
                float2 x = *(const float2*)(s_xsT + ua32 + n2b);
                float2 a = *(const float2*)(s_asT + va32 + n2b);
                r.x = x.x * a.x; r.y = x.y * a.y;
                va32 += 256; if (va32 >= 3072) { va32 -= 3072; ua32 += 32; }
            } else {
                float sx = 0.f, sy = 0.f;
                #pragma unroll
                for (int m = 0; m < 3; m++) {
                    float2 x = *(const float2*)(s_xvT + m * 1024 + uu32 + n2b);
                    float2 a = *(const float2*)(s_avT + m * 1024 + vv32 + n2b);
                    sx = fmaf(x.x, a.x, sx); sy = fmaf(x.y, a.y, sy);
                }
                r.x = INV_SQRT3 * sx; r.y = INV_SQRT3 * sy;
                vv32 += 256; if (vv32 >= 1024) { vv32 -= 1024; uu32 += 32; }
            }
            return r;
        };

        float* bufC = sCh;
        float* bufF = sCh + 1024;
        {
            float2 b0 = *(const float2*)(pB);
            float2 b1 = *(const float2*)(pB + 2);
            float2 b2 = *(const float2*)(pB + 4);
            pB = (1 == c1) ? pBvv0 : pB + 768;
            float2 a0 = buildA1(0);
            *(float2*)(bufC + stA1) = a0;
            *(float2*)(bufC + 256 + stB1)     = b0;
            *(float2*)(bufC + 256 + stB1 + 2) = b1;
            *(float2*)(bufC + 256 + stB1 + 4) = b2;
        }
        __syncthreads();

        for (int c = 0; c < 112; c++) {
            float2 an, bn0, bn1, bn2;
            const bool pre = (c + 1 < 112);
            if (pre) {
                bn0 = *(const float2*)(pB);
                bn1 = *(const float2*)(pB + 2);
                bn2 = *(const float2*)(pB + 4);
                pB = (c + 2 == c1) ? pBvv0 : pB + 768;
                an = buildA1(c + 1);
            }
            const float* A = bufC;
            const float* B = bufC + 256;
            #pragma unroll
            for (int kk = 0; kk < 8; kk++) {
                float4 a  = *(const float4*)&A[kk * 32 + ng];
                float2 b0 = *(const float2*)&B[kk * 96 + w6];
                float2 b1 = *(const float2*)&B[kk * 96 + w6 + 2];
                float2 b2 = *(const float2*)&B[kk * 96 + w6 + 4];
                acc[0]  = fmaf(a.x, b0.x, acc[0]);
                acc[1]  = fmaf(a.x, b0.y, acc[1]);
                acc[2]  = fmaf(a.x, b1.x, acc[2]);
                acc[3]  = fmaf(a.x, b1.y, acc[3]);
                acc[4]  = fmaf(a.x, b2.x, acc[4]);
                acc[5]  = fmaf(a.x, b2.y, acc[5]);
                acc[6]  = fmaf(a.y, b0.x, acc[6]);
                acc[7]  = fmaf(a.y, b0.y, acc[7]);
                acc[8]  = fmaf(a.y, b1.x, acc[8]);
                acc[9]  = fmaf(a.y, b1.y, acc[9]);
                acc[10] = fmaf(a.y, b2.x, acc[10]);
                acc[11] = fmaf(a.y, b2.y, acc[11]);
                acc[12] = fmaf(a.z, b0.x, acc[12]);
                acc[13] = fmaf(a.z, b0.y, acc[13]);
                acc[14] = fmaf(a.z, b1.x, acc[14]);
                acc[15] = fmaf(a.z, b1.y, acc[15]);
                acc[16] = fmaf(a.z, b2.x, acc[16]);
                acc[17] = fmaf(a.z, b2.y, acc[17]);
                acc[18] = fmaf(a.w, b0.x, acc[18]);
                acc[19] = fmaf(a.w, b0.y, acc[19]);
                acc[20] = fmaf(a.w, b1.x, acc[20]);
                acc[21] = fmaf(a.w, b1.y, acc[21]);
                acc[22] = fmaf(a.w, b2.x, acc[22]);
                acc[23] = fmaf(a.w, b2.y, acc[23]);
            }
            if (pre) {
                *(float2*)(bufF + stA1) = an;
                *(float2*)(bufF + 256 + stB1)     = bn0;
                *(float2*)(bufF + 256 + stB1 + 2) = bn1;
                *(float2*)(bufF + 256 + stB1 + 4) = bn2;
            }
            __syncthreads();
            float* tmp = bufC; bufC = bufF; bufF = tmp;
        }
        #pragma unroll
        for (int i = 0; i < 4; i++) {
            int gn = n0 + ng + i;
            if (gn < N_NODES) {
                #pragma unroll
                for (int j = 0; j < 6; j++)
                    atomicAdd(&g_upd[gn * 192 + w6 + j], acc[i * 6 + j]);
            }
        }
    }
    __syncthreads();

    // ---------------- stage 2: uv partial, 80 chunks of 8 ----------------
    {
        const int k_off = slice * 640;
        int c1 = (2048 - k_off) >> 3;
        if (c1 < 0) c1 = 0; if (c1 > 80) c1 = 80;

        const int w4 = (t & 7) * 4;
        const int r6 = (t >> 3) * 6;
        float acc[24];
        #pragma unroll
        for (int i = 0; i < 24; i++) acc[i] = 0.f;

        int rn[6], rm[6];
        #pragma unroll
        for (int j = 0; j < 6; j++) {
            int r = r6b + j;
            rn[j] = r & 31;
            rm[j] = (r >> 5) * 1024 + (r & 31);
        }

        const int ka0 = k_off + kb;
        int su32 = (ka0 >> 5) * 32;
        int sv32 = (ka0 & 31) * 32;
        const int k2c1 = k_off + c1 * 8 + kb - 2048;
        int vu32 = (k2c1 / 96) * 32;
        int vv32 = (k2c1 - (k2c1 / 96) * 96) * 32;
        const float* pBvs0 = Wvs + k2c1 * 32 + w2B;
        const float* pB = (c1 > 0) ? (Wsv + ka0 * 32 + w2B) : pBvs0;

        auto buildA2 = [&](int cc, float* o) {
            if (cc < c1) {
                #pragma unroll
                for (int j = 0; j < 6; j++)
                    o[j] = s_xsT[su32 + rn[j]] * s_avT[rm[j] + sv32];
                sv32 += 256; if (sv32 >= 1024) { sv32 -= 1024; su32 += 32; }
            } else {
                #pragma unroll
                for (int j = 0; j < 6; j++)
                    o[j] = s_xvT[rm[j] + vu32] * s_asT[vv32 + rn[j]];
                vv32 += 256; if (vv32 >= 3072) { vv32 -= 3072; vu32 += 32; }
            }
        };

        float* bufC = sCh;
        float* bufF = sCh + 1024;
        {
            float2 b = *(const float2*)(pB);
            pB = (1 == c1) ? pBvs0 : pB + 256;
            float o[6];
            buildA2(0, o);
            *(float2*)(bufC + stA2)     = *(float2*)&o[0];
            *(float2*)(bufC + stA2 + 2) = *(float2*)&o[2];
            *(float2*)(bufC + stA2 + 4) = *(float2*)&o[4];
            *(float2*)(bufC + 768 + stB2) = b;
        }
        __syncthreads();

        for (int c = 0; c < 80; c++) {
            float on[6];
            float2 bn;
            const bool pre = (c + 1 < 80);
            if (pre) {
                bn = *(const float2*)(pB);
                pB = (c + 2 == c1) ? pBvs0 : pB + 256;
                buildA2(c + 1, on);
            }
            const float* A = bufC;
            const float* B = bufC + 768;
            #pragma unroll
            for (int kk = 0; kk < 8; kk++) {
                float2 a01 = *(const float2*)&A[kk * 96 + r6];
                float2 a23 = *(const float2*)&A[kk * 96 + r6 + 2];
                float2 a45 = *(const float2*)&A[kk * 96 + r6 + 4];
                float4 b   = *(const float4*)&B[kk * 32 + w4];
                acc[0]  = fmaf(a01.x, b.x, acc[0]);
                acc[1]  = fmaf(a01.x, b.y, acc[1]);
                acc[2]  = fmaf(a01.x, b.z, acc[2]);
                acc[3]  = fmaf(a01.x, b.w, acc[3]);
                acc[4]  = fmaf(a01.y, b.x, acc[4]);
                acc[5]  = fmaf(a01.y, b.y, acc[5]);
                acc[6]  = fmaf(a01.y, b.z, acc[6]);
                acc[7]  = fmaf(a01.y, b.w, acc[7]);
                acc[8]  = fmaf(a23.x, b.x, acc[8]);
                acc[9]  = fmaf(a23.x, b.y, acc[9]);
                acc[10] = fmaf(a23.x, b.z, acc[10]);
                acc[11] = fmaf(a23.x, b.w, acc[11]);
                acc[12] = fmaf(a23.y, b.x, acc[12]);
                acc[13] = fmaf(a23.y, b.y, acc[13]);
                acc[14] = fmaf(a23.y, b.z, acc[14]);
                acc[15] = fmaf(a23.y, b.w, acc[15]);
                acc[16] = fmaf(a45.x, b.x, acc[16]);
                acc[17] = fmaf(a45.x, b.y, acc[17]);
                acc[18] = fmaf(a45.x, b.z, acc[18]);
                acc[19] = fmaf(a45.x, b.w, acc[19]);
                acc[20] = fmaf(a45.y, b.x, acc[20]);
                acc[21] = fmaf(a45.y, b.y, acc[21]);
                acc[22] = fmaf(a45.y, b.z, acc[22]);
                acc[23] = fmaf(a45.y, b.w, acc[23]);
            }
            if (pre) {
                *(float2*)(bufF + stA2)     = *(float2*)&on[0];
                *(float2*)(bufF + stA2 + 2) = *(float2*)&on[2];
                *(float2*)(bufF + stA2 + 4) = *(float2*)&on[4];
                *(float2*)(bufF + 768 + stB2) = bn;
            }
            __syncthreads();
            float* tmp = bufC; bufC = bufF; bufF = tmp;
        }
        #pragma unroll
        for (int i = 0; i < 6; i++) {
            int r = r6 + i, m = r >> 5, n = r & 31;
            int gn = n0 + n;
            if (gn < N_NODES) {
                #pragma unroll
                for (int j = 0; j < 4; j++)
                    atomicAdd(&g_upd[gn * 192 + 96 + (w4 + j) * 3 + m],
                              acc[i * 4 + j]);
            }
        }
    }
}

// ============================================================================
// EPILOGUE: norm + gate + linear + residual.  (unchanged)
// ============================================================================
__global__ void __launch_bounds__(128) epilogue_kernel(
    const float* __restrict__ nf,
    const float* __restrict__ WLs, const float* __restrict__ WLv,
    float* __restrict__ out)
{
    __shared__ float s_WLs[4096];
    __shared__ float s_WLv[1024];
    __shared__ float s_us[3072];
    __shared__ float s_uv[3072];

    const int t  = threadIdx.x;
    const int n0 = blockIdx.x * 32;

    for (int i = t; i < 4096; i += 128) s_WLs[i] = WLs[i];
    for (int i = t; i < 1024; i += 128) s_WLv[i] = WLv[i];
    for (int i = t; i < 3072; i += 128) {
        int n = i / 96, c = i - n * 96;
        int gn = n0 + n;
        float us = 0.f, uv = 0.f;
        if (gn < N_NODES) {
            us = g_upd[gn * 192 + c];
            uv = g_upd[gn * 192 + 96 + c];
        }
        s_us[i] = us; s_uv[i] = uv;
    }
    __syncthreads();

    for (int i = t; i < 2048; i += 128) {
        int n = i >> 6, u = i & 63;
        float x = s_us[n * 96 + u] * NORM_UPD_S;
        s_us[n * 96 + u] = x / (1.f + expf(-x));
    }
    for (int i = t; i < 1024; i += 128) {
        int n = i >> 5, w = i & 31;
        float x = s_us[n * 96 + 64 + w] * NORM_UPD_S;
        s_us[n * 96 + 64 + w] = 1.f / (1.f + expf(-x));
    }
    __syncthreads();
    for (int i = t; i < 3072; i += 128) {
        int n = i / 96, c = i - n * 96;
        int u = c / 3;
        s_uv[i] = s_uv[i] * NORM_UPD_V * s_us[n * 96 + 64 + u];
    }
    __syncthreads();

    for (int i = t; i < 2048; i += 128) {
        int n = i >> 6, w = i & 63;
        int gn = n0 + n;
        if (gn < N_NODES) {
            float s = 0.f;
            #pragma unroll 8
            for (int u = 0; u < 64; u++)
                s = fmaf(s_us[n * 96 + u], s_WLs[u * 64 + w], s);
            out[gn * 160 + w] = nf[gn * 160 + w] + s * NORM_LIN64;
        }
    }
    for (int i = t; i < 3072; i += 128) {
        int n = i / 96, c = i - n * 96;
        int w = c / 3, m = c - w * 3;
        int gn = n0 + n;
        if (gn < N_NODES) {
            float s = 0.f;
            #pragma unroll
            for (int u = 0; u < 32; u++)
                s = fmaf(s_uv[n * 96 + u * 3 + m], s_WLv[u * 32 + w], s);
            out[gn * 160 + 64 + c] = nf[gn * 160 + 64 + c] + s * NORM_LIN32;
        }
    }
}

extern "C" void kernel_launch(void* const* d_in, const int* in_sizes, int n_in,
                              void* d_out, int out_size) {
    const float* nf   = (const float*)d_in[0];
    const float* ea   = (const float*)d_in[1];
    const float* Wmss = (const float*)d_in[2];
    const float* Wmvv = (const float*)d_in[3];
    const float* Wmsv = (const float*)d_in[4];
    const float* Wmvs = (const float*)d_in[5];
    const float* WLms = (const float*)d_in[6];
    const float* WLmv = (const float*)d_in[7];
    const float* Wuss = (const float*)d_in[8];
    const float* Wuvv = (const float*)d_in[9];
    const float* Wusv = (const float*)d_in[10];
    const float* Wuvs = (const float*)d_in[11];
    const float* WLus = (const float*)d_in[12];
    const float* WLuv = (const float*)d_in[13];
    const int*   eidx = (const int*)d_in[14];
    float* out = (float*)d_out;

    cudaFuncSetAttribute(node_kernel, cudaFuncAttributeMaxDynamicSharedMemorySize,
                         NODE_SMEM_BYTES);
    cudaFuncSetAttribute(node_kernel, cudaFuncAttributePreferredSharedMemoryCarveout,
                         100);
    cudaFuncSetAttribute(edge_kernel, cudaFuncAttributeMaxDynamicSharedMemorySize,
                         EDGE_SMEM_BYTES);

    zero_kernel<<<(N_NODES * 192 + 255) / 256, 256>>>();
    precompute_z<<<(N_NODES + 31) / 32, 256>>>(nf, Wmss, Wmvv, Wmsv, Wmvs);
    edge_kernel<<<N_EDGES / EB, 256, EDGE_SMEM_BYTES>>>(ea, WLms, WLmv, eidx);
    node_kernel<<<KSPLIT * ((N_NODES + 31) / 32), 128, NODE_SMEM_BYTES>>>(
        nf, Wuss, Wuvv, Wusv, Wuvs);
    epilogue_kernel<<<(N_NODES + 31) / 32, 128>>>(nf, WLus, WLuv, out);
}

// round 17
// speedup vs baseline: 1.0756x; 1.0756x over previous
#include <cuda_runtime.h>
#include <math.h>

#define N_NODES 10000
#define N_EDGES 100000

#define INV_SQRT3    0.57735026918962576f
#define NORM_MSG     0.036084391824351614f   // 1/sqrt(768)
#define NORM_MSG_V3  (0.036084391824351614f * 0.57735026918962576f)
#define NORM_UPD_S   0.011811391307201575f   // 1/sqrt(7168)
#define NORM_UPD_V   0.013975424859373686f   // 1/sqrt(5120)
#define NORM_LIN64   0.125f                  // 1/sqrt(64)
#define NORM_LIN32   0.17677669529663687f    // 1/sqrt(32)

#define ZSTRIDE 4096
// per-node factored message tensor product (norms folded in):
// [0,768) Zss[v<8][w<96], [768,3072) Zvv[(v*3+m)<24][w<96],
// [3072,3328) Zsv[v<8][w<32], [3328,4096) Zvs[v<8][(w*3+m)<96]
__device__ float g_z[(size_t)N_NODES * ZSTRIDE];
__device__ float g_aggp[N_NODES * 160];  // gated pre-linear sums: ps[64] | pv[u*3+m]
__device__ float g_agg[N_NODES * 192];   // post-linear agg: [96 s | 32x3 v] per node
__device__ float g_upd[N_NODES * 192];   // raw partial sums: us[96] | uv[u*3+m]

__global__ void zero_kernel() {
    int i = blockIdx.x * blockDim.x + threadIdx.x;
    if (i < N_NODES * 192) g_upd[i] = 0.f;
    if (i < N_NODES * 160) g_aggp[i] = 0.f;
}

// ============================================================================
// Z PRECOMPUTE v2 (committed): 32 nodes/block, 256 threads, reg-tiled GEMMs.
// ============================================================================
__global__ void __launch_bounds__(256) precompute_z(
    const float* __restrict__ nf,
    const float* __restrict__ Wss, const float* __restrict__ Wvv,
    const float* __restrict__ Wsv, const float* __restrict__ Wvs)
{
    __shared__ float s_xsT[64 * 32];
    __shared__ float s_xvT[3 * 32 * 32];
    __shared__ float s_W[64 * 64];

    const int t  = threadIdx.x;
    const int n0 = blockIdx.x * 32;

    for (int i = t; i < 32 * 160; i += 256) {
        int n = i / 160, c = i - n * 160;
        int gn = n0 + n;
        float v = (gn < N_NODES) ? nf[(size_t)gn * 160 + c] : 0.f;
        if (c < 64) s_xsT[c * 32 + n] = v;
        else { int c2 = c - 64, u = c2 / 3, m = c2 - u * 3;
               s_xvT[m * 1024 + u * 32 + n] = v; }
    }
    __syncthreads();

    const int tc = t & 31;
    const int tn = t >> 5;
    const int c2 = tc * 2;
    const int n4 = tn * 4;
    const int gnb = n0 + n4;

    for (int p = 0; p < 12; p++) {
        for (int idx = t; idx < 4096; idx += 256) {
            int u = idx >> 6, cc = idx & 63;
            s_W[idx] = Wss[u * 768 + p * 64 + cc];
        }
        __syncthreads();
        float acc[8];
        #pragma unroll
        for (int i = 0; i < 8; i++) acc[i] = 0.f;
        #pragma unroll 8
        for (int u = 0; u < 64; u++) {
            float2 w = *(const float2*)&s_W[u * 64 + c2];
            float4 x = *(const float4*)&s_xsT[u * 32 + n4];
            acc[0] = fmaf(w.x, x.x, acc[0]);
            acc[1] = fmaf(w.x, x.y, acc[1]);
            acc[2] = fmaf(w.x, x.z, acc[2]);
            acc[3] = fmaf(w.x, x.w, acc[3]);
            acc[4] = fmaf(w.y, x.x, acc[4]);
            acc[5] = fmaf(w.y, x.y, acc[5]);
            acc[6] = fmaf(w.y, x.z, acc[6]);
            acc[7] = fmaf(w.y, x.w, acc[7]);
        }
        #pragma unroll
        for (int nn = 0; nn < 4; nn++) {
            int gn = gnb + nn;
            if (gn < N_NODES) {
                float2 o = { acc[nn] * NORM_MSG, acc[4 + nn] * NORM_MSG };
                *(float2*)&g_z[(size_t)gn * ZSTRIDE + p * 64 + c2] = o;
            }
        }
        __syncthreads();
    }

    for (int m = 0; m < 3; m++) {
        const float* xm = s_xvT + m * 1024;
        for (int p = 0; p < 12; p++) {
            for (int idx = t; idx < 2048; idx += 256) {
                int u = idx >> 6, cc = idx & 63;
                s_W[idx] = Wvv[u * 768 + p * 64 + cc];
            }
            __syncthreads();
            float acc[8];
            #pragma unroll
            for (int i = 0; i < 8; i++) acc[i] = 0.f;
            #pragma unroll 8
            for (int u = 0; u < 32; u++) {
                float2 w = *(const float2*)&s_W[u * 64 + c2];
                float4 x = *(const float4*)&xm[u * 32 + n4];
                acc[0] = fmaf(w.x, x.x, acc[0]);
                acc[1] = fmaf(w.x, x.y, acc[1]);
                acc[2] = fmaf(w.x, x.z, acc[2]);
                acc[3] = fmaf(w.x, x.w, acc[3]);
                acc[4] = fmaf(w.y, x.x, acc[4]);
                acc[5] = fmaf(w.y, x.y, acc[5]);
                acc[6] = fmaf(w.y, x.z, acc[6]);
                acc[7] = fmaf(w.y, x.w, acc[7]);
            }
            int cm = p * 64 + c2;
            int v  = cm / 96;
            int col = 768 + v * 288 + m * 96 + (cm - v * 96);
            #pragma unroll
            for (int nn = 0; nn < 4; nn++) {
                int gn = gnb + nn;
                if (gn < N_NODES) {
                    float2 o = { acc[nn] * NORM_MSG_V3, acc[4 + nn] * NORM_MSG_V3 };
                    *(float2*)&g_z[(size_t)gn * ZSTRIDE + col] = o;
                }
            }
            __syncthreads();
        }
    }

    for (int p = 0; p < 4; p++) {
        for (int idx = t; idx < 4096; idx += 256) {
            int u = idx >> 6, cc = idx & 63;
            s_W[idx] = Wsv[u * 256 + p * 64 + cc];
        }
        __syncthreads();
        float acc[8];
        #pragma unroll
        for (int i = 0; i < 8; i++) acc[i] = 0.f;
        #pragma unroll 8
        for (int u = 0; u < 64; u++) {
            float2 w = *(const float2*)&s_W[u * 64 + c2];
            float4 x = *(const float4*)&s_xsT[u * 32 + n4];
            acc[0] = fmaf(w.x, x.x, acc[0]);
            acc[1] = fmaf(w.x, x.y, acc[1]);
            acc[2] = fmaf(w.x, x.z, acc[2]);
            acc[3] = fmaf(w.x, x.w, acc[3]);
            acc[4] = fmaf(w.y, x.x, acc[4]);
            acc[5] = fmaf(w.y, x.y, acc[5]);
            acc[6] = fmaf(w.y, x.z, acc[6]);
            acc[7] = fmaf(w.y, x.w, acc[7]);
        }
        #pragma unroll
        for (int nn = 0; nn < 4; nn++) {
            int gn = gnb + nn;
            if (gn < N_NODES) {
                float2 o = { acc[nn] * NORM_MSG, acc[4 + nn] * NORM_MSG };
                *(float2*)&g_z[(size_t)gn * ZSTRIDE + 3072 + p * 64 + c2] = o;
            }
        }
        __syncthreads();
    }

    for (int p = 0; p < 8; p++) {
        for (int idx = t; idx < 1024; idx += 256) {
            int u = idx >> 5, cw = idx & 31;
            s_W[idx] = Wvs[u * 256 + p * 32 + cw];
        }
        __syncthreads();
        float acc[12];
        #pragma unroll
        for (int i = 0; i < 12; i++) acc[i] = 0.f;
        #pragma unroll 8
        for (int u = 0; u < 32; u++) {
            float w = s_W[u * 32 + tc];
            #pragma unroll
            for (int m = 0; m < 3; m++) {
                float4 x = *(const float4*)&s_xvT[m * 1024 + u * 32 + n4];
                acc[m * 4 + 0] = fmaf(w, x.x, acc[m * 4 + 0]);
                acc[m * 4 + 1] = fmaf(w, x.y, acc[m * 4 + 1]);
                acc[m * 4 + 2] = fmaf(w, x.z, acc[m * 4 + 2]);
                acc[m * 4 + 3] = fmaf(w, x.w, acc[m * 4 + 3]);
            }
        }
        int cw = p * 32 + tc;
        int v  = cw >> 5, ww = cw & 31;
        int colb = 3328 + v * 96 + ww * 3;
        #pragma unroll
        for (int nn = 0; nn < 4; nn++) {
            int gn = gnb + nn;
            if (gn < N_NODES) {
                float* dst = &g_z[(size_t)gn * ZSTRIDE + colb];
                #pragma unroll
                for (int m = 0; m < 3; m++)
                    dst[m] = acc[m * 4 + nn] * NORM_MSG;
            }
        }
        __syncthreads();
    }
}

// ============================================================================
// EDGE KERNEL v4: warp-per-edge TP + gate + DIRECT scatter of gated message.
// Linear layer moved out (commutes with segment_sum). ~1KB smem, max occ.
// ============================================================================
#define EB 8
__global__ void __launch_bounds__(256) edge_kernel(
    const float* __restrict__ ea, const int* __restrict__ eidx)
{
    __shared__ float s_y[EB * 32];
    const int t = threadIdx.x;
    const int es = t >> 5, l = t & 31;
    const int e = blockIdx.x * EB + es;
    s_y[es * 32 + l] = ea[(size_t)e * 32 + l];
    __syncwarp();

    const int row = eidx[e];
    const int col = eidx[N_EDGES + e];
    const float* Z  = g_z + (size_t)col * ZSTRIDE;
    const float* ye = s_y + es * 32;

    float a0 = 0.f, a1 = 0.f, a2 = 0.f;
    #pragma unroll 8
    for (int q = 0; q < 32; q++) {
        float y = ye[q];
        const float* zr = Z + q * 96;
        a0 = fmaf(y, zr[l],      a0);
        a1 = fmaf(y, zr[l + 32], a1);
        a2 = fmaf(y, zr[l + 64], a2);
    }
    const size_t base = (size_t)row * 160;
    atomicAdd(&g_aggp[base + l],      a0 / (1.f + expf(-a0)));
    atomicAdd(&g_aggp[base + 32 + l], a1 / (1.f + expf(-a1)));
    float g = 1.f / (1.f + expf(-a2));    // gate for vector channel w = l

    const float* Zsv = Z + 3072;
    const float* Zvs = Z + 3328;
    #pragma unroll
    for (int cc = 0; cc < 3; cc++) {
        int c = l + cc * 32;
        int w = c / 3, m = c - w * 3;
        float acc = 0.f;
        #pragma unroll
        for (int v = 0; v < 8; v++) {
            acc = fmaf(ye[v],             Zvs[v * 96 + c], acc);
            acc = fmaf(ye[8 + v * 3 + m], Zsv[v * 32 + w], acc);
        }
        float gw = __shfl_sync(0xffffffffu, g, w);
        atomicAdd(&g_aggp[base + 64 + c], acc * gw);
    }
}

// ============================================================================
// AGG LINEAR: apply message linear ONCE per node (post scatter-sum).
// g_agg[n][w<96] = (sum ps) @ WLs / 8 ;  g_agg[n][96+w*3+m] = (sum pv) @ WLv / sqrt32
// ============================================================================
__global__ void __launch_bounds__(128) agg_linear_kernel(
    const float* __restrict__ WLs, const float* __restrict__ WLv)
{
    __shared__ float s_WLs[6144];
    __shared__ float s_WLv[1024];
    __shared__ float s_p[32 * 160];
    const int t  = threadIdx.x;
    const int n0 = blockIdx.x * 32;

    for (int i = t; i < 6144; i += 128) s_WLs[i] = WLs[i];
    for (int i = t; i < 1024; i += 128) s_WLv[i] = WLv[i];
    for (int i = t; i < 32 * 160; i += 128) {
        int n = i / 160, c = i - n * 160;
        int gn = n0 + n;
        s_p[i] = (gn < N_NODES) ? g_aggp[(size_t)gn * 160 + c] : 0.f;
    }
    __syncthreads();

    for (int i = t; i < 32 * 96; i += 128) {
        int n = i / 96, w = i - n * 96;
        int gn = n0 + n;
        if (gn < N_NODES) {
            float s = 0.f;
            #pragma unroll 8
            for (int u = 0; u < 64; u++)
                s = fmaf(s_p[n * 160 + u], s_WLs[u * 96 + w], s);
            g_agg[gn * 192 + w] = s * NORM_LIN64;
        }
    }
    for (int i = t; i < 32 * 96; i += 128) {
        int n = i / 96, c = i - n * 96;
        int w = c / 3, m = c - w * 3;
        int gn = n0 + n;
        if (gn < N_NODES) {
            float s = 0.f;
            #pragma unroll
            for (int u = 0; u < 32; u++)
                s = fmaf(s_p[n * 160 + 64 + u * 3 + m], s_WLv[u * 32 + w], s);
            g_agg[gn * 192 + 96 + c] = s * NORM_LIN32;
        }
    }
}

// ============================================================================
// NODE KERNEL v7 (committed @716us): ALU-free steady state, 8-way K-split,
// Kc=8, 128 threads, 4 blocks/SM.
// ============================================================================
#define KSPLIT 8
#define NODE_SMEM_BYTES (13312 * 4)

__global__ void __launch_bounds__(128, 4) node_kernel(
    const float* __restrict__ nf,
    const float* __restrict__ Wss, const float* __restrict__ Wvv,
    const float* __restrict__ Wsv, const float* __restrict__ Wvs)
{
    extern __shared__ float sm[];
    float* s_xsT = sm;
    float* s_xvT = sm + 2048;
    float* s_asT = sm + 5120;
    float* s_avT = sm + 8192;
    float* sCh   = sm + 11264;   // 2 x 1024

    const int t     = threadIdx.x;
    const int tile  = blockIdx.x >> 3;
    const int slice = blockIdx.x & 7;
    const int n0    = tile * 32;

    for (int i = t; i < 32 * 160; i += 128) {
        int n = i / 160, c = i - n * 160;
        int gn = n0 + n;
        float v = (gn < N_NODES) ? nf[gn * 160 + c] : 0.f;
        if (c < 64) s_xsT[c * 32 + n] = v;
        else { int c2 = c - 64, u = c2 / 3, m = c2 - u * 3;
               s_xvT[m * 1024 + u * 32 + n] = v; }
    }
    for (int i = t; i < 32 * 192; i += 128) {
        int n = i / 192, c = i - n * 192;
        int gn = n0 + n;
        float v = (gn < N_NODES) ? g_agg[gn * 192 + c] : 0.f;
        if (c < 96) s_asT[c * 32 + n] = v;
        else { int c2 = c - 96, w = c2 / 3, m = c2 - w * 3;
               s_avT[m * 1024 + w * 32 + n] = v; }
    }
    __syncthreads();

    const int kb  = t >> 4;
    const int n2b = (t & 15) * 2;
    const int wB6 = (t & 15) * 6;
    const int r6b = (t & 15) * 6;
    const int w2B = (t & 15) * 2;
    const int stA1 = kb * 32 + n2b;
    const int stB1 = kb * 96 + wB6;
    const int stA2 = kb * 96 + r6b;
    const int stB2 = kb * 32 + w2B;

    // ---------------- stage 1: us partial, 112 chunks of 8 ----------------
    {
        const int k_off = slice * 896;
        int c1 = (6144 - k_off) >> 3;
        if (c1 < 0) c1 = 0; if (c1 > 112) c1 = 112;

        const int ng = (t & 7) * 4;
        const int w6 = (t >> 3) * 6;
        float acc[24];
        #pragma unroll
        for (int i = 0; i < 24; i++) acc[i] = 0.f;

        const int ka0 = k_off + kb;
        int ua32 = (ka0 / 96) * 32;
        int va32 = (ka0 - (ka0 / 96) * 96) * 32;
        const int k2c1 = k_off + c1 * 8 + kb - 6144;
        int uu32 = (k2c1 >> 5) * 32;
        int vv32 = (k2c1 & 31) * 32;
        const float* pBvv0 = Wvv + k2c1 * 96 + wB6;
        const float* pB = (c1 > 0) ? (Wss + ka0 * 96 + wB6) : pBvv0;

        auto buildA1 = [&](int cc) -> float2 {
            float2 r;
            if (cc < c1) {
                float2 x = *(const float2*)(s_xsT + ua32 + n2b);
                float2 a = *(const float2*)(s_asT + va32 + n2b);
                r.x = x.x * a.x; r.y = x.y * a.y;
                va32 += 256; if (va32 >= 3072) { va32 -= 3072; ua32 += 32; }
            } else {
                float sx = 0.f, sy = 0.f;
                #pragma unroll
                for (int m = 0; m < 3; m++) {
                    float2 x = *(const float2*)(s_xvT + m * 1024 + uu32 + n2b);
                    float2 a = *(const float2*)(s_avT + m * 1024 + vv32 + n2b);
                    sx = fmaf(x.x, a.x, sx); sy = fmaf(x.y, a.y, sy);
                }
                r.x = INV_SQRT3 * sx; r.y = INV_SQRT3 * sy;
                vv32 += 256; if (vv32 >= 1024) { vv32 -= 1024; uu32 += 32; }
            }
            return r;
        };

        float* bufC = sCh;
        float* bufF = sCh + 1024;
        {
            float2 b0 = *(const float2*)(pB);
            float2 b1 = *(const float2*)(pB + 2);
            float2 b2 = *(const float2*)(pB + 4);
            pB = (1 == c1) ? pBvv0 : pB + 768;
            float2 a0 = buildA1(0);
            *(float2*)(bufC + stA1) = a0;
            *(float2*)(bufC + 256 + stB1)     = b0;
            *(float2*)(bufC + 256 + stB1 + 2) = b1;
            *(float2*)(bufC + 256 + stB1 + 4) = b2;
        }
        __syncthreads();

        for (int c = 0; c < 112; c++) {
            float2 an, bn0, bn1, bn2;
            const bool pre = (c + 1 < 112);
            if (pre) {
                bn0 = *(const float2*)(pB);
                bn1 = *(const float2*)(pB + 2);
                bn2 = *(const float2*)(pB + 4);
                pB = (c + 2 == c1) ? pBvv0 : pB + 768;
                an = buildA1(c + 1);
            }
            const float* A = bufC;
            const float* B = bufC + 256;
            #pragma unroll
            for (int kk = 0; kk < 8; kk++) {
                float4 a  = *(const float4*)&A[kk * 32 + ng];
                float2 b0 = *(const float2*)&B[kk * 96 + w6];
                float2 b1 = *(const float2*)&B[kk * 96 + w6 + 2];
                float2 b2 = *(const float2*)&B[kk * 96 + w6 + 4];
                acc[0]  = fmaf(a.x, b0.x, acc[0]);
                acc[1]  = fmaf(a.x, b0.y, acc[1]);
                acc[2]  = fmaf(a.x, b1.x, acc[2]);
                acc[3]  = fmaf(a.x, b1.y, acc[3]);
                acc[4]  = fmaf(a.x, b2.x, acc[4]);
                acc[5]  = fmaf(a.x, b2.y, acc[5]);
                acc[6]  = fmaf(a.y, b0.x, acc[6]);
                acc[7]  = fmaf(a.y, b0.y, acc[7]);
                acc[8]  = fmaf(a.y, b1.x, acc[8]);
                acc[9]  = fmaf(a.y, b1.y, acc[9]);
                acc[10] = fmaf(a.y, b2.x, acc[10]);
                acc[11] = fmaf(a.y, b2.y, acc[11]);
                acc[12] = fmaf(a.z, b0.x, acc[12]);
                acc[13] = fmaf(a.z, b0.y, acc[13]);
                acc[14] = fmaf(a.z, b1.x, acc[14]);
                acc[15] = fmaf(a.z, b1.y, acc[15]);
                acc[16] = fmaf(a.z, b2.x, acc[16]);
                acc[17] = fmaf(a.z, b2.y, acc[17]);
                acc[18] = fmaf(a.w, b0.x, acc[18]);
                acc[19] = fmaf(a.w, b0.y, acc[19]);
                acc[20] = fmaf(a.w, b1.x, acc[20]);
                acc[21] = fmaf(a.w, b1.y, acc[21]);
                acc[22] = fmaf(a.w, b2.x, acc[22]);
                acc[23] = fmaf(a.w, b2.y, acc[23]);
            }
            if (pre) {
                *(float2*)(bufF + stA1) = an;
                *(float2*)(bufF + 256 + stB1)     = bn0;
                *(float2*)(bufF + 256 + stB1 + 2) = bn1;
                *(float2*)(bufF + 256 + stB1 + 4) = bn2;
            }
            __syncthreads();
            float* tmp = bufC; bufC = bufF; bufF = tmp;
        }
        #pragma unroll
        for (int i = 0; i < 4; i++) {
            int gn = n0 + ng + i;
            if (gn < N_NODES) {
                #pragma unroll
                for (int j = 0; j < 6; j++)
                    atomicAdd(&g_upd[gn * 192 + w6 + j], acc[i * 6 + j]);
            }
        }
    }
    __syncthreads();

    // ---------------- stage 2: uv partial, 80 chunks of 8 ----------------
    {
        const int k_off = slice * 640;
        int c1 = (2048 - k_off) >> 3;
        if (c1 < 0) c1 = 0; if (c1 > 80) c1 = 80;

        const int w4 = (t & 7) * 4;
        const int r6 = (t >> 3) * 6;
        float acc[24];
        #pragma unroll
        for (int i = 0; i < 24; i++) acc[i] = 0.f;

        int rn[6], rm[6];
        #pragma unroll
        for (int j = 0; j < 6; j++) {
            int r = r6b + j;
            rn[j] = r & 31;
            rm[j] = (r >> 5) * 1024 + (r & 31);
        }

        const int ka0 = k_off + kb;
        int su32 = (ka0 >> 5) * 32;
        int sv32 = (ka0 & 31) * 32;
        const int k2c1 = k_off + c1 * 8 + kb - 2048;
        int vu32 = (k2c1 / 96) * 32;
        int vv32 = (k2c1 - (k2c1 / 96) * 96) * 32;
        const float* pBvs0 = Wvs + k2c1 * 32 + w2B;
        const float* pB = (c1 > 0) ? (Wsv + ka0 * 32 + w2B) : pBvs0;

        auto buildA2 = [&](int cc, float* o) {
            if (cc < c1) {
                #pragma unroll
                for (int j = 0; j < 6; j++)
                    o[j] = s_xsT[su32 + rn[j]] * s_avT[rm[j] + sv32];
                sv32 += 256; if (sv32 >= 1024) { sv32 -= 1024; su32 += 32; }
            } else {
                #pragma unroll
                for (int j = 0; j < 6; j++)
                    o[j] = s_xvT[rm[j] + vu32] * s_asT[vv32 + rn[j]];
                vv32 += 256; if (vv32 >= 3072) { vv32 -= 3072; vu32 += 32; }
            }
        };

        float* bufC = sCh;
        float* bufF = sCh + 1024;
        {
            float2 b = *(const float2*)(pB);
            pB = (1 == c1) ? pBvs0 : pB + 256;
            float o[6];
            buildA2(0, o);
            *(float2*)(bufC + stA2)     = *(float2*)&o[0];
            *(float2*)(bufC + stA2 + 2) = *(float2*)&o[2];
            *(float2*)(bufC + stA2 + 4) = *(float2*)&o[4];
            *(float2*)(bufC + 768 + stB2) = b;
        }
        __syncthreads();

        for (int c = 0; c < 80; c++) {
            float on[6];
            float2 bn;
            const bool pre = (c + 1 < 80);
            if (pre) {
                bn = *(const float2*)(pB);
                pB = (c + 2 == c1) ? pBvs0 : pB + 256;
                buildA2(c + 1, on);
            }
            const float* A = bufC;
            const float* B = bufC + 768;
            #pragma unroll
            for (int kk = 0; kk < 8; kk++) {
                float2 a01 = *(const float2*)&A[kk * 96 + r6];
                float2 a23 = *(const float2*)&A[kk * 96 + r6 + 2];
                float2 a45 = *(const float2*)&A[kk * 96 + r6 + 4];
                float4 b   = *(const float4*)&B[kk * 32 + w4];
                acc[0]  = fmaf(a01.x, b.x, acc[0]);
                acc[1]  = fmaf(a01.x, b.y, acc[1]);
                acc[2]  = fmaf(a01.x, b.z, acc[2]);
                acc[3]  = fmaf(a01.x, b.w, acc[3]);
                acc[4]  = fmaf(a01.y, b.x, acc[4]);
                acc[5]  = fmaf(a01.y, b.y, acc[5]);
                acc[6]  = fmaf(a01.y, b.z, acc[6]);
                acc[7]  = fmaf(a01.y, b.w, acc[7]);
                acc[8]  = fmaf(a23.x, b.x, acc[8]);
                acc[9]  = fmaf(a23.x, b.y, acc[9]);
                acc[10] = fmaf(a23.x, b.z, acc[10]);
                acc[11] = fmaf(a23.x, b.w, acc[11]);
                acc[12] = fmaf(a23.y, b.x, acc[12]);
                acc[13] = fmaf(a23.y, b.y, acc[13]);
                acc[14] = fmaf(a23.y, b.z, acc[14]);
                acc[15] = fmaf(a23.y, b.w, acc[15]);
                acc[16] = fmaf(a45.x, b.x, acc[16]);
                acc[17] = fmaf(a45.x, b.y, acc[17]);
                acc[18] = fmaf(a45.x, b.z, acc[18]);
                acc[19] = fmaf(a45.x, b.w, acc[19]);
                acc[20] = fmaf(a45.y, b.x, acc[20]);
                acc[21] = fmaf(a45.y, b.y, acc[21]);
                acc[22] = fmaf(a45.y, b.z, acc[22]);
                acc[23] = fmaf(a45.y, b.w, acc[23]);
            }
            if (pre) {
                *(float2*)(bufF + stA2)     = *(float2*)&on[0];
                *(float2*)(bufF + stA2 + 2) = *(float2*)&on[2];
                *(float2*)(bufF + stA2 + 4) = *(float2*)&on[4];
                *(float2*)(bufF + 768 + stB2) = bn;
            }
            __syncthreads();
            float* tmp = bufC; bufC = bufF; bufF = tmp;
        }
        #pragma unroll
        for (int i = 0; i < 6; i++) {
            int r = r6 + i, m = r >> 5, n = r & 31;
            int gn = n0 + n;
            if (gn < N_NODES) {
                #pragma unroll
                for (int j = 0; j < 4; j++)
                    atomicAdd(&g_upd[gn * 192 + 96 + (w4 + j) * 3 + m],
                              acc[i * 4 + j]);
            }
        }
    }
}

// ============================================================================
// EPILOGUE: norm + gate + linear + residual.  (unchanged)
// ============================================================================
__global__ void __launch_bounds__(128) epilogue_kernel(
    const float* __restrict__ nf,
    const float* __restrict__ WLs, const float* __restrict__ WLv,
    float* __restrict__ out)
{
    __shared__ float s_WLs[4096];
    __shared__ float s_WLv[1024];
    __shared__ float s_us[3072];
    __shared__ float s_uv[3072];

    const int t  = threadIdx.x;
    const int n0 = blockIdx.x * 32;

    for (int i = t; i < 4096; i += 128) s_WLs[i] = WLs[i];
    for (int i = t; i < 1024; i += 128) s_WLv[i] = WLv[i];
    for (int i = t; i < 3072; i += 128) {
        int n = i / 96, c = i - n * 96;
        int gn = n0 + n;
        float us = 0.f, uv = 0.f;
        if (gn < N_NODES) {
            us = g_upd[gn * 192 + c];
            uv = g_upd[gn * 192 + 96 + c];
        }
        s_us[i] = us; s_uv[i] = uv;
    }
    __syncthreads();

    for (int i = t; i < 2048; i += 128) {
        int n = i >> 6, u = i & 63;
        float x = s_us[n * 96 + u] * NORM_UPD_S;
        s_us[n * 96 + u] = x / (1.f + expf(-x));
    }
    for (int i = t; i < 1024; i += 128) {
        int n = i >> 5, w = i & 31;
        float x = s_us[n * 96 + 64 + w] * NORM_UPD_S;
        s_us[n * 96 + 64 + w] = 1.f / (1.f + expf(-x));
    }
    __syncthreads();
    for (int i = t; i < 3072; i += 128) {
        int n = i / 96, c = i - n * 96;
        int u = c / 3;
        s_uv[i] = s_uv[i] * NORM_UPD_V * s_us[n * 96 + 64 + u];
    }
    __syncthreads();

    for (int i = t; i < 2048; i += 128) {
        int n = i >> 6, w = i & 63;
        int gn = n0 + n;
        if (gn < N_NODES) {
            float s = 0.f;
            #pragma unroll 8
            for (int u = 0; u < 64; u++)
                s = fmaf(s_us[n * 96 + u], s_WLs[u * 64 + w], s);
            out[gn * 160 + w] = nf[gn * 160 + w] + s * NORM_LIN64;
        }
    }
    for (int i = t; i < 3072; i += 128) {
        int n = i / 96, c = i - n * 96;
        int w = c / 3, m = c - w * 3;
        int gn = n0 + n;
        if (gn < N_NODES) {
            float s = 0.f;
            #pragma unroll
            for (int u = 0; u < 32; u++)
                s = fmaf(s_uv[n * 96 + u * 3 + m], s_WLv[u * 32 + w], s);
            out[gn * 160 + 64 + c] = nf[gn * 160 + 64 + c] + s * NORM_LIN32;
        }
    }
}

extern "C" void kernel_launch(void* const* d_in, const int* in_sizes, int n_in,
                              void* d_out, int out_size) {
    const float* nf   = (const float*)d_in[0];
    const float* ea   = (const float*)d_in[1];
    const float* Wmss = (const float*)d_in[2];
    const float* Wmvv = (const float*)d_in[3];
    const float* Wmsv = (const float*)d_in[4];
    const float* Wmvs = (const float*)d_in[5];
    const float* WLms = (const float*)d_in[6];
    const float* WLmv = (const float*)d_in[7];
    const float* Wuss = (const float*)d_in[8];
    const float* Wuvv = (const float*)d_in[9];
    const float* Wusv = (const float*)d_in[10];
    const float* Wuvs = (const float*)d_in[11];
    const float* WLus = (const float*)d_in[12];
    const float* WLuv = (const float*)d_in[13];
    const int*   eidx = (const int*)d_in[14];
    float* out = (float*)d_out;

    cudaFuncSetAttribute(node_kernel, cudaFuncAttributeMaxDynamicSharedMemorySize,
                         NODE_SMEM_BYTES);
    cudaFuncSetAttribute(node_kernel, cudaFuncAttributePreferredSharedMemoryCarveout,
                         100);

    zero_kernel<<<(N_NODES * 192 + 255) / 256, 256>>>();
    precompute_z<<<(N_NODES + 31) / 32, 256>>>(nf, Wmss, Wmvv, Wmsv, Wmvs);
    edge_kernel<<<N_EDGES / EB, 256>>>(ea, eidx);
    agg_linear_kernel<<<(N_NODES + 31) / 32, 128>>>(WLms, WLmv);
    node_kernel<<<KSPLIT * ((N_NODES + 31) / 32), 128, NODE_SMEM_BYTES>>>(
        nf, Wuss, Wuvv, Wusv, Wuvs);
    epilogue_kernel<<<(N_NODES + 31) / 32, 128>>>(nf, WLus, WLuv, out);
}